// round 11
// baseline (speedup 1.0000x reference)
#include <cuda_runtime.h>
#include <cuda_fp16.h>
#include <cstdint>

#define NB 4
#define SL 2048
#define EQ 512
#define ET 512
#define NH 8
#define EH 64
#define NF 8

typedef __half fp16;

// ---------------- scratch (device globals; no allocation allowed) ----------------
__device__ __align__(16) fp16 g_qh   [NB * SL * EQ];    // query, single fp16 (gemm1 A)
__device__ __align__(16) fp16 g_wh   [EQ * 3 * ET];     // Wqkv hi/lo (gemm1 B, [K,N])
__device__ __align__(16) fp16 g_wl   [EQ * 3 * ET];
__device__ __align__(16) fp16 g_qkvh [NB * SL * 3 * ET];   // qkv fp16 (q pre-scaled 1/8)
__device__ __align__(16) fp16 g_oh   [NB * SL * ET];    // attention out fp16 (gemm2 A)
__device__ __align__(16) fp16 g_weffh[NF * ET * EQ];    // fused forecast weights fp16 ([K,N])

// ---------------- PTX helpers ----------------
__device__ __forceinline__ uint32_t sptr(const void* p) {
    return (uint32_t)__cvta_generic_to_shared(p);
}
__device__ __forceinline__ void cpasync16(uint32_t s, const void* g) {
    asm volatile("cp.async.cg.shared.global [%0], [%1], 16;\n" :: "r"(s), "l"(g));
}
__device__ __forceinline__ void cpcommit() {
    asm volatile("cp.async.commit_group;\n");
}
template<int N> __device__ __forceinline__ void cpwait() {
    asm volatile("cp.async.wait_group %0;\n" :: "n"(N));
}
__device__ __forceinline__ void ldsm4(uint32_t* r, uint32_t a) {
    asm volatile("ldmatrix.sync.aligned.m8n8.x4.shared.b16 {%0,%1,%2,%3},[%4];\n"
                 : "=r"(r[0]), "=r"(r[1]), "=r"(r[2]), "=r"(r[3]) : "r"(a));
}
__device__ __forceinline__ void ldsm4t(uint32_t* r, uint32_t a) {
    asm volatile("ldmatrix.sync.aligned.m8n8.x4.trans.shared.b16 {%0,%1,%2,%3},[%4];\n"
                 : "=r"(r[0]), "=r"(r[1]), "=r"(r[2]), "=r"(r[3]) : "r"(a));
}
__device__ __forceinline__ void mmah(float* c, const uint32_t* a, uint32_t b0, uint32_t b1) {
    asm volatile("mma.sync.aligned.m16n8k16.row.col.f32.f16.f16.f32 "
                 "{%0,%1,%2,%3},{%4,%5,%6,%7},{%8,%9},{%0,%1,%2,%3};\n"
                 : "+f"(c[0]), "+f"(c[1]), "+f"(c[2]), "+f"(c[3])
                 : "r"(a[0]), "r"(a[1]), "r"(a[2]), "r"(a[3]), "r"(b0), "r"(b1));
}
__device__ __forceinline__ uint32_t packh(fp16 a, fp16 b) {
    __half2 t = __halves2half2(a, b);
    return *(uint32_t*)&t;
}

// ---------------- fused fp32 -> fp16 splits (query hi; Wqkv hi/lo) ----------------
#define NQ4 (NB * SL * EQ / 4)
#define NW4 (EQ * 3 * ET / 4)

__global__ void __launch_bounds__(256)
split_all_kernel(const float* __restrict__ q, const float* __restrict__ w,
                 fp16* __restrict__ qh, fp16* __restrict__ wh, fp16* __restrict__ wl)
{
    int i = blockIdx.x * 256 + threadIdx.x;
    if (i < NQ4) {
        float4 v = ((const float4*)q)[i];
        ((__half2*)qh)[2 * i]     = __halves2half2(__float2half_rn(v.x), __float2half_rn(v.y));
        ((__half2*)qh)[2 * i + 1] = __halves2half2(__float2half_rn(v.z), __float2half_rn(v.w));
    } else if (i < NQ4 + NW4) {
        int j = i - NQ4;
        float4 v = ((const float4*)w)[j];
        fp16 h0 = __float2half_rn(v.x), h1 = __float2half_rn(v.y);
        fp16 h2 = __float2half_rn(v.z), h3 = __float2half_rn(v.w);
        ((__half2*)wh)[2 * j]     = __halves2half2(h0, h1);
        ((__half2*)wh)[2 * j + 1] = __halves2half2(h2, h3);
        ((__half2*)wl)[2 * j]     = __halves2half2(
            __float2half_rn(v.x - __half2float(h0)),
            __float2half_rn(v.y - __half2float(h1)));
        ((__half2*)wl)[2 * j + 1] = __halves2half2(
            __float2half_rn(v.z - __half2float(h2)),
            __float2half_rn(v.w - __half2float(h3)));
    }
}

// ---------------- fp16 tensor-core GEMM ----------------
// P==2: C = Ah(Bh+Bl)  — gemm1;  P==1: C = Ah·Bh — gemm2. 128x128x32 tiles, 8 warps.
template<int P>
__global__ void __launch_bounds__(256)
mma_gemm(const fp16* __restrict__ Ah_, const fp16* __restrict__ Bh_,
         const fp16* __restrict__ Bl_,
         const float* __restrict__ bias, float* __restrict__ C,
         fp16* __restrict__ Ch, int qscaleCols,
         int M, int N, int K, size_t aB, size_t bB, size_t cB)
{
    constexpr int BHOc = 5120;
    constexpr int BLOc = BHOc + 4352;
    constexpr int GSc  = BHOc + ((P >= 2) ? 8704 : 4352);

    extern __shared__ fp16 sm[];
    int z = blockIdx.z;
    Ah_ += (size_t)(z >> 3) * aB;
    Bh_ += (size_t)(z & 7) * bB;
    if (P >= 2) Bl_ += (size_t)(z & 7) * bB;

    int tid = threadIdx.x, lane = tid & 31, wid = tid >> 5;
    int wm = wid >> 2, wn = wid & 3;
    int m0 = blockIdx.y * 128, n0c = blockIdx.x * 128;
    uint32_t sbase = sptr(sm);

    int ar = tid >> 1, ac = (tid & 1) * 16;
    int br = tid >> 3, bc = (tid & 7) * 16;

    auto loadTile = [&](int kt, int buf) {
        int k0 = kt * 32;
        uint32_t sb = sbase + buf * GSc * 2;
        const fp16* ag = Ah_ + (size_t)(m0 + ar) * K + k0 + ac;
        cpasync16(sb + (ar * 40 + ac) * 2, ag);
        cpasync16(sb + (ar * 40 + ac + 8) * 2, ag + 8);
        const fp16* bg = Bh_ + (size_t)(k0 + br) * N + n0c + bc;
        cpasync16(sb + (BHOc + br * 136 + bc) * 2, bg);
        cpasync16(sb + (BHOc + br * 136 + bc + 8) * 2, bg + 8);
        if (P >= 2) {
            const fp16* bg2 = Bl_ + (size_t)(k0 + br) * N + n0c + bc;
            cpasync16(sb + (BLOc + br * 136 + bc) * 2, bg2);
            cpasync16(sb + (BLOc + br * 136 + bc + 8) * 2, bg2 + 8);
        }
        cpcommit();
    };

    float acc[4][4][4];
#pragma unroll
    for (int i = 0; i < 4; i++)
#pragma unroll
        for (int j = 0; j < 4; j++)
#pragma unroll
            for (int k = 0; k < 4; k++) acc[i][j][k] = 0.f;

    int nk = K / 32;
    loadTile(0, 0);
    for (int kt = 0; kt < nk; kt++) {
        if (kt + 1 < nk) { loadTile(kt + 1, (kt + 1) & 1); cpwait<1>(); }
        else             { cpwait<0>(); }
        __syncthreads();
        uint32_t sb = sbase + (kt & 1) * GSc * 2;

#pragma unroll
        for (int ks = 0; ks < 2; ks++) {
            int k0 = ks * 16;
            uint32_t ah[4][4];
            int arow = wm * 64 + (lane & 15);
            int acol = k0 + ((lane >> 4) << 3);
#pragma unroll
            for (int mi = 0; mi < 4; mi++)
                ldsm4(ah[mi], sb + ((arow + mi * 16) * 40 + acol) * 2);
            uint32_t bh[2][4], bl[2][4];
            int brow = k0 + (lane & 7) + ((lane >> 4) << 3);
            int bcol = wn * 32 + ((lane >> 3) & 1) * 8;
#pragma unroll
            for (int g = 0; g < 2; g++) {
                ldsm4t(bh[g], sb + (BHOc + brow * 136 + bcol + g * 16) * 2);
                if (P >= 2)
                    ldsm4t(bl[g], sb + (BLOc + brow * 136 + bcol + g * 16) * 2);
            }
#pragma unroll
            for (int mi = 0; mi < 4; mi++)
#pragma unroll
                for (int nf = 0; nf < 4; nf++) {
                    int g = nf >> 1, s = nf & 1;
                    if (P >= 2)
                        mmah(acc[mi][nf], ah[mi], bl[g][s], bl[g][s + 2]);
                    mmah(acc[mi][nf], ah[mi], bh[g][s], bh[g][s + 2]);
                }
        }
        __syncthreads();
    }

#pragma unroll
    for (int mi = 0; mi < 4; mi++)
#pragma unroll
        for (int nf = 0; nf < 4; nf++) {
            int r = m0 + wm * 64 + mi * 16 + (lane >> 2);
            int c = n0c + wn * 32 + nf * 8 + (lane & 3) * 2;
            float b0 = bias[c], b1 = bias[c + 1];
            float v00 = acc[mi][nf][0] + b0, v01 = acc[mi][nf][1] + b1;
            float v10 = acc[mi][nf][2] + b0, v11 = acc[mi][nf][3] + b1;
            if (qscaleCols && c < qscaleCols) {
                v00 *= 0.125f; v01 *= 0.125f; v10 *= 0.125f; v11 *= 0.125f;
            }
            if (Ch) {
                size_t i0 = (size_t)z * cB + (size_t)r * N + c;
                size_t i1 = i0 + (size_t)8 * N;
                *(__half2*)(Ch + i0) = __halves2half2(__float2half_rn(v00), __float2half_rn(v01));
                *(__half2*)(Ch + i1) = __halves2half2(__float2half_rn(v10), __float2half_rn(v11));
            } else {
                float* Cz = C + (size_t)z * cB;
                *(float2*)(Cz + (size_t)r * N + c) = make_float2(v00, v01);
                *(float2*)(Cz + (size_t)(r + 8) * N + c) = make_float2(v10, v11);
            }
        }
}

// ---------------- tensor-core causal flash attention, d=64, BQ=128, BKV=64 ----------
// Static-max softmax p=exp(s-4) (exact; offset cancels). 3-stage cp.async pipeline,
// ONE __syncthreads per tile (loads issued post-barrier), Q fragments hoisted.
#define ASTR 72
#define QH_OFF 0
#define KV_OFF 9216
#define KVSTAGE 9216
#define ATTN_SMEM ((9216 + 3 * 9216) * 2)

__global__ void __launch_bounds__(256, 2)
attn_kernel()
{
    extern __shared__ fp16 smb[];
    int qt = 15 - blockIdx.x;
    int bh = blockIdx.y;
    int b = bh >> 3, h = bh & 7;
    int tid = threadIdx.x, lane = tid & 31, w = tid >> 5;
    int q0 = qt * 128;
    int hoff = h * EH;
    const fp16* qkvh = g_qkvh + (size_t)b * SL * 1536;

    // Q: rides stage-0 commit group
    {
        int chunk = tid & 7;
        int row = tid >> 3;
#pragma unroll
        for (int it = 0; it < 4; it++) {
            int r = row + it * 32;
            cpasync16(sptr(smb + QH_OFF + r * ASTR + chunk * 8),
                      qkvh + (size_t)(q0 + r) * 1536 + hoff + chunk * 8);
        }
    }
    auto loadKV = [&](int kt, int stage) {
        int kv0 = kt * 64;
        fp16* base = smb + KV_OFF + stage * KVSTAGE;
        int chunk = tid & 7;
        int row = tid >> 3;
#pragma unroll
        for (int it = 0; it < 4; it++) {
            int arr = it >> 1;
            int r = row + (it & 1) * 32;
            int colbase = (arr == 0) ? (ET + hoff) : (2 * ET + hoff);
            cpasync16(sptr(base + arr * 4608 + r * ASTR + chunk * 8),
                      qkvh + (size_t)(kv0 + r) * 1536 + colbase + chunk * 8);
        }
        cpcommit();
    };

    int kmax = 2 * qt + 1;        // >= 1 always
    loadKV(0, 0);                 // group 0 (includes Q)
    loadKV(1, 1);                 // group 1

    float l0 = 0.f, l1 = 0.f;
    float oc[8][4];
#pragma unroll
    for (int i = 0; i < 8; i++)
#pragma unroll
        for (int j = 0; j < 4; j++) oc[i][j] = 0.f;

    int arow = w * 16 + (lane & 15);
    int acolsel = (lane >> 4) << 3;
    int krow = (lane & 7) + ((lane >> 4) << 3);
    int kcolsel = ((lane >> 3) & 1) << 3;
    int vrowbase = krow;

    // stage 0 + Q ready
    cpwait<1>();
    __syncthreads();

    // hoisted Q fragments (loop-invariant)
    uint32_t qf[4][4];
#pragma unroll
    for (int kc = 0; kc < 4; kc++)
        ldsm4(qf[kc], sptr(smb + QH_OFF + arow * ASTR + kc * 16 + acolsel));

    for (int kt = 0; kt <= kmax; kt++) {
        if (kt > 0) {
            cpwait<1>();          // group kt done (group kt+1 may remain)
            __syncthreads();
        }
        // issue stage kt+2 AFTER the barrier (buffer (kt-1)%3 now reusable)
        if (kt + 2 <= kmax) loadKV(kt + 2, (kt + 2) % 3);
        else                cpcommit();   // empty group keeps accounting exact

        fp16* base = smb + KV_OFF + (kt % 3) * KVSTAGE;
        fp16* KH = base;
        fp16* VH = base + 4608;

        // ---- S = Qh Kh^T ----
        float sc[8][4];
#pragma unroll
        for (int i = 0; i < 8; i++)
#pragma unroll
            for (int j = 0; j < 4; j++) sc[i][j] = 0.f;

#pragma unroll
        for (int kc = 0; kc < 4; kc++) {
            int kcol = kc * 16 + kcolsel;
#pragma unroll
            for (int g = 0; g < 4; g++) {
                uint32_t b4h[4];
                ldsm4(b4h, sptr(KH + (g * 16 + krow) * ASTR + kcol));
                mmah(sc[2 * g],     qf[kc], b4h[0], b4h[1]);
                mmah(sc[2 * g + 1], qf[kc], b4h[2], b4h[3]);
            }
        }

        // ---- causal mask (diagonal tiles only) ----
        if (kt >= 2 * qt) {
            int kv0 = kt * 64;
            int r0 = q0 + w * 16 + (lane >> 2);
#pragma unroll
            for (int nf = 0; nf < 8; nf++) {
                int c0 = kv0 + nf * 8 + (lane & 3) * 2;
                if (c0 > r0)     sc[nf][0] = -1e30f;
                if (c0 + 1 > r0) sc[nf][1] = -1e30f;
                if (c0 > r0 + 8)     sc[nf][2] = -1e30f;
                if (c0 + 1 > r0 + 8) sc[nf][3] = -1e30f;
            }
        }

        // ---- static-offset exp + local l accumulation ----
#pragma unroll
        for (int nf = 0; nf < 8; nf++) {
            sc[nf][0] = __expf(sc[nf][0] - 4.f);
            sc[nf][1] = __expf(sc[nf][1] - 4.f);
            sc[nf][2] = __expf(sc[nf][2] - 4.f);
            sc[nf][3] = __expf(sc[nf][3] - 4.f);
            l0 += sc[nf][0] + sc[nf][1];
            l1 += sc[nf][2] + sc[nf][3];
        }

        // ---- O += P Vh ----
#pragma unroll
        for (int kc = 0; kc < 4; kc++) {
            uint32_t pah[4];
#pragma unroll
            for (int half = 0; half < 2; half++) {
                int nf = 2 * kc + half;
                pah[half * 2 + 0] = packh(__float2half_rn(sc[nf][0]),
                                          __float2half_rn(sc[nf][1]));
                pah[half * 2 + 1] = packh(__float2half_rn(sc[nf][2]),
                                          __float2half_rn(sc[nf][3]));
            }
            int vrow = kc * 16 + vrowbase;
#pragma unroll
            for (int g = 0; g < 4; g++) {
                int vcol = g * 16 + kcolsel;
                uint32_t v4h[4];
                ldsm4t(v4h, sptr(VH + vrow * ASTR + vcol));
                mmah(oc[2 * g],     pah, v4h[0], v4h[2]);
                mmah(oc[2 * g + 1], pah, v4h[1], v4h[3]);
            }
        }
    }

    // final row-sum reduction
    l0 += __shfl_xor_sync(0xffffffffu, l0, 1);
    l0 += __shfl_xor_sync(0xffffffffu, l0, 2);
    l1 += __shfl_xor_sync(0xffffffffu, l1, 1);
    l1 += __shfl_xor_sync(0xffffffffu, l1, 2);

    float inv0 = 1.f / l0, inv1 = 1.f / l1;
    int row0 = q0 + w * 16 + (lane >> 2);
    size_t ob = (size_t)b * SL * ET;
#pragma unroll
    for (int nf = 0; nf < 8; nf++) {
        int col = hoff + nf * 8 + (lane & 3) * 2;
        size_t i0 = ob + (size_t)row0 * ET + col;
        size_t i1 = ob + (size_t)(row0 + 8) * ET + col;
        *(__half2*)(g_oh + i0) = __halves2half2(
            __float2half_rn(oc[nf][0] * inv0), __float2half_rn(oc[nf][1] * inv0));
        *(__half2*)(g_oh + i1) = __halves2half2(
            __float2half_rn(oc[nf][2] * inv1), __float2half_rn(oc[nf][3] * inv1));
    }
}

// ---------------- fused: W_eff[n] rows h*64.. = M_h^(n+1) @ Wo_h ----------------
__global__ void __launch_bounds__(256)
powweff_kernel(const float* __restrict__ Xi, const float* __restrict__ Wo)
{
    extern __shared__ float pw[];
    float* Mh = pw;
    float* R  = pw + 4352;
    float* RT = pw + 2 * 4352;
    int idx = blockIdx.x;
    int half = idx & 1;
    int nh = idx >> 1;
    int n = nh >> 3, h = nh & 7;
    int tid = threadIdx.x;
    const float* X = Xi + h * 64 * 64;

#pragma unroll
    for (int t = 0; t < 16; t++) {
        int id2 = tid + t * 256;
        int i = id2 >> 6, j = id2 & 63;
        float v = X[i * 64 + j] - X[j * 64 + i];
        if (i == j) v += 1.f;
        Mh[i * 68 + j] = v;
        R [i * 68 + j] = v;
        RT[j * 68 + i] = v;
    }
    __syncthreads();

    int i0 = (tid >> 4) * 4, j0 = (tid & 15) * 4;
    auto mult = [&](const float* B) {
        float acc[4][4];
#pragma unroll
        for (int a = 0; a < 4; a++)
#pragma unroll
            for (int bq = 0; bq < 4; bq++) acc[a][bq] = 0.f;
#pragma unroll 4
        for (int k = 0; k < 64; k++) {
            float4 av = *(const float4*)&RT[k * 68 + i0];
            float4 bv = *(const float4*)&B[k * 68 + j0];
            float aa[4] = {av.x, av.y, av.z, av.w};
            float bb[4] = {bv.x, bv.y, bv.z, bv.w};
#pragma unroll
            for (int a = 0; a < 4; a++)
#pragma unroll
                for (int bq = 0; bq < 4; bq++)
                    acc[a][bq] = fmaf(aa[a], bb[bq], acc[a][bq]);
        }
        __syncthreads();
#pragma unroll
        for (int a = 0; a < 4; a++)
#pragma unroll
            for (int bq = 0; bq < 4; bq++) {
                R [(i0 + a) * 68 + j0 + bq] = acc[a][bq];
                RT[(j0 + bq) * 68 + i0 + a] = acc[a][bq];
            }
        __syncthreads();
    };

    int e = n + 1;
    if (e > 1) {
        int msb = 31 - __clz(e);
        for (int bpos = msb - 1; bpos >= 0; bpos--) {
            mult(R);
            if ((e >> bpos) & 1) mult(Mh);
        }
    }

    int c = half * 256 + tid;
    const float* WoH = Wo + (size_t)h * 64 * EQ;
    size_t ob = (size_t)n * ET * EQ + (size_t)h * 64 * EQ;
    float acc[4][16];
#pragma unroll
    for (int p = 0; p < 4; p++)
#pragma unroll
        for (int ii = 0; ii < 16; ii++) acc[p][ii] = 0.f;
    for (int j = 0; j < 64; j++) {
        float wv = WoH[j * EQ + c];
        const float* row = &RT[j * 68];
#pragma unroll
        for (int p = 0; p < 4; p++) {
#pragma unroll
            for (int q4 = 0; q4 < 4; q4++) {
                float4 rv = *(const float4*)&row[p * 16 + q4 * 4];
                acc[p][q4 * 4 + 0] = fmaf(rv.x, wv, acc[p][q4 * 4 + 0]);
                acc[p][q4 * 4 + 1] = fmaf(rv.y, wv, acc[p][q4 * 4 + 1]);
                acc[p][q4 * 4 + 2] = fmaf(rv.z, wv, acc[p][q4 * 4 + 2]);
                acc[p][q4 * 4 + 3] = fmaf(rv.w, wv, acc[p][q4 * 4 + 3]);
            }
        }
    }
#pragma unroll
    for (int p = 0; p < 4; p++)
#pragma unroll
        for (int ii = 0; ii < 16; ii++)
            g_weffh[ob + (size_t)(p * 16 + ii) * EQ + c] = __float2half_rn(acc[p][ii]);
}

// ---------------- launch ----------------
extern "C" void kernel_launch(void* const* d_in, const int* in_sizes, int n_in,
                              void* d_out, int out_size)
{
    const float* query = (const float*)d_in[0];
    const float* Wqkv  = (const float*)d_in[3];
    const float* bqkv  = (const float*)d_in[4];
    const float* Wo    = (const float*)d_in[5];
    const float* bo    = (const float*)d_in[6];
    const float* Xi    = (const float*)d_in[7];
    float* out = (float*)d_out;

    fp16 *qh, *wh, *wl, *qkvh, *oh, *weh;
    cudaGetSymbolAddress((void**)&qh, g_qh);
    cudaGetSymbolAddress((void**)&wh, g_wh);
    cudaGetSymbolAddress((void**)&wl, g_wl);
    cudaGetSymbolAddress((void**)&qkvh, g_qkvh);
    cudaGetSymbolAddress((void**)&oh, g_oh);
    cudaGetSymbolAddress((void**)&weh, g_weffh);

    constexpr int SM2 = 2 * 13824 * 2;
    constexpr int SM1 = 2 * 9472 * 2;
    cudaFuncSetAttribute(mma_gemm<2>, cudaFuncAttributeMaxDynamicSharedMemorySize, SM2);
    cudaFuncSetAttribute(mma_gemm<1>, cudaFuncAttributeMaxDynamicSharedMemorySize, SM1);
    cudaFuncSetAttribute(attn_kernel, cudaFuncAttributeMaxDynamicSharedMemorySize, ATTN_SMEM);
    cudaFuncSetAttribute(powweff_kernel, cudaFuncAttributeMaxDynamicSharedMemorySize, 3 * 4352 * 4);

    // 0) fused fp16 splits (query hi; Wqkv hi/lo) — single launch
    split_all_kernel<<<(NQ4 + NW4 + 255) / 256, 256>>>(query, Wqkv, qh, wh, wl);

    // 1) QKV projection (2-product) -> fp16 qkv, q cols pre-scaled by 1/8
    dim3 g1(3 * ET / 128, NB * SL / 128, 1);
    mma_gemm<2><<<g1, 256, SM2>>>(qh, wh, wl, bqkv, nullptr, qkvh, EQ,
                                  NB * SL, 3 * ET, EQ, 0, 0, (size_t)0);

    // 2) fused matrix powers + forecast weights
    powweff_kernel<<<2 * NF * NH, 256, 3 * 4352 * 4>>>(Xi, Wo);

    // 3) causal flash attention (static-max softmax, 3-stage pipe) -> fp16 attn out
    attn_kernel<<<dim3(SL / 128, NB * NH), 256, ATTN_SMEM>>>();

    // 4) fused forecast+output projection (1-product) -> fp32 out
    dim3 g2(EQ / 128, SL / 128, NB * NF);
    mma_gemm<1><<<g2, 256, SM1>>>(oh, weh, nullptr, bo, out, nullptr, 0,
                                  SL, EQ, ET,
                                  (size_t)SL * ET, (size_t)ET * EQ, (size_t)SL * EQ);
}

// round 12
// speedup vs baseline: 1.1288x; 1.1288x over previous
#include <cuda_runtime.h>
#include <cuda_fp16.h>
#include <cstdint>

#define NB 4
#define SL 2048
#define EQ 512
#define ET 512
#define NH 8
#define EH 64
#define NF 8

typedef __half fp16;

// q pre-scale includes log2(e) so attention can use raw ex2: (1/8)*log2(e)
#define QSCALE 0.18033688f
#define EXP2_OFF 5.7707802f     // 4 * log2(e)

// ---------------- scratch (device globals; no allocation allowed) ----------------
__device__ __align__(16) fp16 g_qh   [NB * SL * EQ];
__device__ __align__(16) fp16 g_wh   [EQ * 3 * ET];
__device__ __align__(16) fp16 g_wl   [EQ * 3 * ET];
__device__ __align__(16) fp16 g_qkvh [NB * SL * 3 * ET];
__device__ __align__(16) fp16 g_oh   [NB * SL * ET];
__device__ __align__(16) fp16 g_weffh[NF * ET * EQ];

// ---------------- PTX helpers ----------------
__device__ __forceinline__ uint32_t sptr(const void* p) {
    return (uint32_t)__cvta_generic_to_shared(p);
}
__device__ __forceinline__ void cpasync16(uint32_t s, const void* g) {
    asm volatile("cp.async.cg.shared.global [%0], [%1], 16;\n" :: "r"(s), "l"(g));
}
__device__ __forceinline__ void cpcommit() {
    asm volatile("cp.async.commit_group;\n");
}
template<int N> __device__ __forceinline__ void cpwait() {
    asm volatile("cp.async.wait_group %0;\n" :: "n"(N));
}
__device__ __forceinline__ void ldsm4(uint32_t* r, uint32_t a) {
    asm volatile("ldmatrix.sync.aligned.m8n8.x4.shared.b16 {%0,%1,%2,%3},[%4];\n"
                 : "=r"(r[0]), "=r"(r[1]), "=r"(r[2]), "=r"(r[3]) : "r"(a));
}
__device__ __forceinline__ void ldsm4t(uint32_t* r, uint32_t a) {
    asm volatile("ldmatrix.sync.aligned.m8n8.x4.trans.shared.b16 {%0,%1,%2,%3},[%4];\n"
                 : "=r"(r[0]), "=r"(r[1]), "=r"(r[2]), "=r"(r[3]) : "r"(a));
}
__device__ __forceinline__ void mmah(float* c, const uint32_t* a, uint32_t b0, uint32_t b1) {
    asm volatile("mma.sync.aligned.m16n8k16.row.col.f32.f16.f16.f32 "
                 "{%0,%1,%2,%3},{%4,%5,%6,%7},{%8,%9},{%0,%1,%2,%3};\n"
                 : "+f"(c[0]), "+f"(c[1]), "+f"(c[2]), "+f"(c[3])
                 : "r"(a[0]), "r"(a[1]), "r"(a[2]), "r"(a[3]), "r"(b0), "r"(b1));
}
__device__ __forceinline__ uint32_t packh(fp16 a, fp16 b) {
    __half2 t = __halves2half2(a, b);
    return *(uint32_t*)&t;
}
__device__ __forceinline__ float ex2(float x) {
    float y;
    asm("ex2.approx.ftz.f32 %0, %1;" : "=f"(y) : "f"(x));
    return y;
}

// ---------------- prep: split (query hi, Wqkv hi/lo)  ∥  powweff ----------------
#define NQ4 (NB * SL * EQ / 4)
#define NW4 (EQ * 3 * ET / 4)
#define PREP_PW_BLOCKS (2 * NF * NH)                       // 128
#define PREP_SPLIT_BLOCKS ((NQ4 + NW4 + 255) / 256)
#define PREP_SMEM (3 * 4352 * 4)

__global__ void __launch_bounds__(256)
prep_kernel(const float* __restrict__ query, const float* __restrict__ Wqkv,
            const float* __restrict__ Xi, const float* __restrict__ Wo,
            fp16* __restrict__ qh, fp16* __restrict__ wh, fp16* __restrict__ wl)
{
    int tid = threadIdx.x;
    if (blockIdx.x >= PREP_PW_BLOCKS) {
        // ---- split part ----
        int i = (blockIdx.x - PREP_PW_BLOCKS) * 256 + tid;
        if (i < NQ4) {
            float4 v = ((const float4*)query)[i];
            ((__half2*)qh)[2 * i]     = __halves2half2(__float2half_rn(v.x), __float2half_rn(v.y));
            ((__half2*)qh)[2 * i + 1] = __halves2half2(__float2half_rn(v.z), __float2half_rn(v.w));
        } else if (i < NQ4 + NW4) {
            int j = i - NQ4;
            float4 v = ((const float4*)Wqkv)[j];
            fp16 h0 = __float2half_rn(v.x), h1 = __float2half_rn(v.y);
            fp16 h2 = __float2half_rn(v.z), h3 = __float2half_rn(v.w);
            ((__half2*)wh)[2 * j]     = __halves2half2(h0, h1);
            ((__half2*)wh)[2 * j + 1] = __halves2half2(h2, h3);
            ((__half2*)wl)[2 * j]     = __halves2half2(
                __float2half_rn(v.x - __half2float(h0)),
                __float2half_rn(v.y - __half2float(h1)));
            ((__half2*)wl)[2 * j + 1] = __halves2half2(
                __float2half_rn(v.z - __half2float(h2)),
                __float2half_rn(v.w - __half2float(h3)));
        }
        return;
    }

    // ---- powweff part: W_eff[n] rows h*64.. = M_h^(n+1) @ Wo_h ----
    extern __shared__ float pw[];
    float* Mh = pw;
    float* R  = pw + 4352;
    float* RT = pw + 2 * 4352;
    int idx = blockIdx.x;
    int half = idx & 1;
    int nh = idx >> 1;
    int n = nh >> 3, h = nh & 7;
    const float* X = Xi + h * 64 * 64;

#pragma unroll
    for (int t = 0; t < 16; t++) {
        int id2 = tid + t * 256;
        int i = id2 >> 6, j = id2 & 63;
        float v = X[i * 64 + j] - X[j * 64 + i];
        if (i == j) v += 1.f;
        Mh[i * 68 + j] = v;
        R [i * 68 + j] = v;
        RT[j * 68 + i] = v;
    }
    __syncthreads();

    int i0 = (tid >> 4) * 4, j0 = (tid & 15) * 4;
    auto mult = [&](const float* B) {
        float acc[4][4];
#pragma unroll
        for (int a = 0; a < 4; a++)
#pragma unroll
            for (int bq = 0; bq < 4; bq++) acc[a][bq] = 0.f;
#pragma unroll 4
        for (int k = 0; k < 64; k++) {
            float4 av = *(const float4*)&RT[k * 68 + i0];
            float4 bv = *(const float4*)&B[k * 68 + j0];
            float aa[4] = {av.x, av.y, av.z, av.w};
            float bb[4] = {bv.x, bv.y, bv.z, bv.w};
#pragma unroll
            for (int a = 0; a < 4; a++)
#pragma unroll
                for (int bq = 0; bq < 4; bq++)
                    acc[a][bq] = fmaf(aa[a], bb[bq], acc[a][bq]);
        }
        __syncthreads();
#pragma unroll
        for (int a = 0; a < 4; a++)
#pragma unroll
            for (int bq = 0; bq < 4; bq++) {
                R [(i0 + a) * 68 + j0 + bq] = acc[a][bq];
                RT[(j0 + bq) * 68 + i0 + a] = acc[a][bq];
            }
        __syncthreads();
    };

    int e = n + 1;
    if (e > 1) {
        int msb = 31 - __clz(e);
        for (int bpos = msb - 1; bpos >= 0; bpos--) {
            mult(R);
            if ((e >> bpos) & 1) mult(Mh);
        }
    }

    int c = half * 256 + tid;
    const float* WoH = Wo + (size_t)h * 64 * EQ;
    size_t ob = (size_t)n * ET * EQ + (size_t)h * 64 * EQ;
    float acc[4][16];
#pragma unroll
    for (int p = 0; p < 4; p++)
#pragma unroll
        for (int ii = 0; ii < 16; ii++) acc[p][ii] = 0.f;
    for (int j = 0; j < 64; j++) {
        float wv = WoH[j * EQ + c];
        const float* row = &RT[j * 68];
#pragma unroll
        for (int p = 0; p < 4; p++) {
#pragma unroll
            for (int q4 = 0; q4 < 4; q4++) {
                float4 rv = *(const float4*)&row[p * 16 + q4 * 4];
                acc[p][q4 * 4 + 0] = fmaf(rv.x, wv, acc[p][q4 * 4 + 0]);
                acc[p][q4 * 4 + 1] = fmaf(rv.y, wv, acc[p][q4 * 4 + 1]);
                acc[p][q4 * 4 + 2] = fmaf(rv.z, wv, acc[p][q4 * 4 + 2]);
                acc[p][q4 * 4 + 3] = fmaf(rv.w, wv, acc[p][q4 * 4 + 3]);
            }
        }
    }
#pragma unroll
    for (int p = 0; p < 4; p++)
#pragma unroll
        for (int ii = 0; ii < 16; ii++)
            g_weffh[ob + (size_t)(p * 16 + ii) * EQ + c] = __float2half_rn(acc[p][ii]);
}

// ---------------- fp16 tensor-core GEMM, 128x128 tiles, BK=64, 2 stages ----------
// P==2: C = Ah(Bh+Bl) — gemm1;  P==1: C = Ah·Bh — gemm2.
// A smem [128][72], B smem [64][136] per operand.
template<int P>
__global__ void __launch_bounds__(256)
mma_gemm(const fp16* __restrict__ Ah_, const fp16* __restrict__ Bh_,
         const fp16* __restrict__ Bl_,
         const float* __restrict__ bias, float* __restrict__ C,
         fp16* __restrict__ Ch, int qscaleCols,
         int M, int N, int K, size_t aB, size_t bB, size_t cB)
{
    constexpr int BHOc = 9216;                  // A = 128*72
    constexpr int BLOc = BHOc + 8704;           // B = 64*136
    constexpr int GSc  = BHOc + ((P >= 2) ? 17408 : 8704);

    extern __shared__ fp16 sm[];
    int z = blockIdx.z;
    Ah_ += (size_t)(z >> 3) * aB;
    Bh_ += (size_t)(z & 7) * bB;
    if (P >= 2) Bl_ += (size_t)(z & 7) * bB;

    int tid = threadIdx.x, lane = tid & 31, wid = tid >> 5;
    int wm = wid >> 2, wn = wid & 3;
    int m0 = blockIdx.y * 128, n0c = blockIdx.x * 128;
    uint32_t sbase = sptr(sm);

    int chunk = tid & 7, rowa = tid >> 3;       // A: 8 chunks x 32 rows x4
    int ckb = tid & 15, rowb = tid >> 4;        // B: 16 chunks x 16 rows x4

    auto loadTile = [&](int kt, int buf) {
        int k0 = kt * 64;
        uint32_t sb = sbase + buf * GSc * 2;
#pragma unroll
        for (int rep = 0; rep < 4; rep++) {
            int r = rowa + rep * 32;
            cpasync16(sb + (r * 72 + chunk * 8) * 2,
                      Ah_ + (size_t)(m0 + r) * K + k0 + chunk * 8);
        }
#pragma unroll
        for (int rep = 0; rep < 4; rep++) {
            int r = rowb + rep * 16;
            cpasync16(sb + (BHOc + r * 136 + ckb * 8) * 2,
                      Bh_ + (size_t)(k0 + r) * N + n0c + ckb * 8);
            if (P >= 2)
                cpasync16(sb + (BLOc + r * 136 + ckb * 8) * 2,
                          Bl_ + (size_t)(k0 + r) * N + n0c + ckb * 8);
        }
        cpcommit();
    };

    float acc[4][4][4];
#pragma unroll
    for (int i = 0; i < 4; i++)
#pragma unroll
        for (int j = 0; j < 4; j++)
#pragma unroll
            for (int k = 0; k < 4; k++) acc[i][j][k] = 0.f;

    int arow = wm * 64 + (lane & 15);
    int acolsel = (lane >> 4) << 3;
    int krow = (lane & 7) + ((lane >> 4) << 3);
    int bcol = wn * 32 + ((lane >> 3) & 1) * 8;

    int nk = K / 64;
    loadTile(0, 0);
    for (int kt = 0; kt < nk; kt++) {
        if (kt + 1 < nk) { loadTile(kt + 1, (kt + 1) & 1); cpwait<1>(); }
        else             { cpwait<0>(); }
        __syncthreads();
        uint32_t sb = sbase + (kt & 1) * GSc * 2;

#pragma unroll
        for (int ks = 0; ks < 4; ks++) {
            int acol = ks * 16 + acolsel;
            uint32_t ah[4][4];
#pragma unroll
            for (int mi = 0; mi < 4; mi++)
                ldsm4(ah[mi], sb + ((arow + mi * 16) * 72 + acol) * 2);
            uint32_t bh[2][4], bl[2][4];
            int brow = ks * 16 + krow;
#pragma unroll
            for (int g = 0; g < 2; g++) {
                ldsm4t(bh[g], sb + (BHOc + brow * 136 + bcol + g * 16) * 2);
                if (P >= 2)
                    ldsm4t(bl[g], sb + (BLOc + brow * 136 + bcol + g * 16) * 2);
            }
#pragma unroll
            for (int mi = 0; mi < 4; mi++)
#pragma unroll
                for (int nf = 0; nf < 4; nf++) {
                    int g = nf >> 1, s = nf & 1;
                    if (P >= 2)
                        mmah(acc[mi][nf], ah[mi], bl[g][s], bl[g][s + 2]);
                    mmah(acc[mi][nf], ah[mi], bh[g][s], bh[g][s + 2]);
                }
        }
        __syncthreads();
    }

#pragma unroll
    for (int mi = 0; mi < 4; mi++)
#pragma unroll
        for (int nf = 0; nf < 4; nf++) {
            int r = m0 + wm * 64 + mi * 16 + (lane >> 2);
            int c = n0c + wn * 32 + nf * 8 + (lane & 3) * 2;
            float b0 = bias[c], b1 = bias[c + 1];
            float v00 = acc[mi][nf][0] + b0, v01 = acc[mi][nf][1] + b1;
            float v10 = acc[mi][nf][2] + b0, v11 = acc[mi][nf][3] + b1;
            if (qscaleCols && c < qscaleCols) {
                v00 *= QSCALE; v01 *= QSCALE; v10 *= QSCALE; v11 *= QSCALE;
            }
            if (Ch) {
                size_t i0 = (size_t)z * cB + (size_t)r * N + c;
                size_t i1 = i0 + (size_t)8 * N;
                *(__half2*)(Ch + i0) = __halves2half2(__float2half_rn(v00), __float2half_rn(v01));
                *(__half2*)(Ch + i1) = __halves2half2(__float2half_rn(v10), __float2half_rn(v11));
            } else {
                float* Cz = C + (size_t)z * cB;
                *(float2*)(Cz + (size_t)r * N + c) = make_float2(v00, v01);
                *(float2*)(Cz + (size_t)(r + 8) * N + c) = make_float2(v10, v11);
            }
        }
}

// ---------------- tensor-core causal flash attention, d=64, BQ=128, BKV=64 ----------
// p = exp2(s' - 4*log2e) where s' = q·k·log2(e)/8 (log2e folded into q pre-scale).
// 3-stage cp.async pipeline, one sync per tile, Q fragments hoisted.
#define ASTR 72
#define QH_OFF 0
#define KV_OFF 9216
#define KVSTAGE 9216
#define ATTN_SMEM ((9216 + 3 * 9216) * 2)

__global__ void __launch_bounds__(256, 2)
attn_kernel()
{
    extern __shared__ fp16 smb[];
    int qt = 15 - blockIdx.x;
    int bh = blockIdx.y;
    int b = bh >> 3, h = bh & 7;
    int tid = threadIdx.x, lane = tid & 31, w = tid >> 5;
    int q0 = qt * 128;
    int hoff = h * EH;
    const fp16* qkvh = g_qkvh + (size_t)b * SL * 1536;

    {
        int chunk = tid & 7;
        int row = tid >> 3;
#pragma unroll
        for (int it = 0; it < 4; it++) {
            int r = row + it * 32;
            cpasync16(sptr(smb + QH_OFF + r * ASTR + chunk * 8),
                      qkvh + (size_t)(q0 + r) * 1536 + hoff + chunk * 8);
        }
    }
    auto loadKV = [&](int kt, int stage) {
        int kv0 = kt * 64;
        fp16* base = smb + KV_OFF + stage * KVSTAGE;
        int chunk = tid & 7;
        int row = tid >> 3;
#pragma unroll
        for (int it = 0; it < 4; it++) {
            int arr = it >> 1;
            int r = row + (it & 1) * 32;
            int colbase = (arr == 0) ? (ET + hoff) : (2 * ET + hoff);
            cpasync16(sptr(base + arr * 4608 + r * ASTR + chunk * 8),
                      qkvh + (size_t)(kv0 + r) * 1536 + colbase + chunk * 8);
        }
        cpcommit();
    };

    int kmax = 2 * qt + 1;
    loadKV(0, 0);
    loadKV(1, 1);

    float l0 = 0.f, l1 = 0.f;
    float oc[8][4];
#pragma unroll
    for (int i = 0; i < 8; i++)
#pragma unroll
        for (int j = 0; j < 4; j++) oc[i][j] = 0.f;

    int arow = w * 16 + (lane & 15);
    int acolsel = (lane >> 4) << 3;
    int krow = (lane & 7) + ((lane >> 4) << 3);
    int kcolsel = ((lane >> 3) & 1) << 3;
    int vrowbase = krow;

    cpwait<1>();
    __syncthreads();

    uint32_t qf[4][4];
#pragma unroll
    for (int kc = 0; kc < 4; kc++)
        ldsm4(qf[kc], sptr(smb + QH_OFF + arow * ASTR + kc * 16 + acolsel));

    for (int kt = 0; kt <= kmax; kt++) {
        if (kt > 0) {
            cpwait<1>();
            __syncthreads();
        }
        if (kt + 2 <= kmax) loadKV(kt + 2, (kt + 2) % 3);
        else                cpcommit();

        fp16* base = smb + KV_OFF + (kt % 3) * KVSTAGE;
        fp16* KH = base;
        fp16* VH = base + 4608;

        float sc[8][4];
#pragma unroll
        for (int i = 0; i < 8; i++)
#pragma unroll
            for (int j = 0; j < 4; j++) sc[i][j] = 0.f;

#pragma unroll
        for (int kc = 0; kc < 4; kc++) {
            int kcol = kc * 16 + kcolsel;
#pragma unroll
            for (int g = 0; g < 4; g++) {
                uint32_t b4h[4];
                ldsm4(b4h, sptr(KH + (g * 16 + krow) * ASTR + kcol));
                mmah(sc[2 * g],     qf[kc], b4h[0], b4h[1]);
                mmah(sc[2 * g + 1], qf[kc], b4h[2], b4h[3]);
            }
        }

        if (kt >= 2 * qt) {
            int kv0 = kt * 64;
            int r0 = q0 + w * 16 + (lane >> 2);
#pragma unroll
            for (int nf = 0; nf < 8; nf++) {
                int c0 = kv0 + nf * 8 + (lane & 3) * 2;
                if (c0 > r0)     sc[nf][0] = -1e30f;
                if (c0 + 1 > r0) sc[nf][1] = -1e30f;
                if (c0 > r0 + 8)     sc[nf][2] = -1e30f;
                if (c0 + 1 > r0 + 8) sc[nf][3] = -1e30f;
            }
        }

#pragma unroll
        for (int nf = 0; nf < 8; nf++) {
            sc[nf][0] = ex2(sc[nf][0] - EXP2_OFF);
            sc[nf][1] = ex2(sc[nf][1] - EXP2_OFF);
            sc[nf][2] = ex2(sc[nf][2] - EXP2_OFF);
            sc[nf][3] = ex2(sc[nf][3] - EXP2_OFF);
            l0 += sc[nf][0] + sc[nf][1];
            l1 += sc[nf][2] + sc[nf][3];
        }

#pragma unroll
        for (int kc = 0; kc < 4; kc++) {
            uint32_t pah[4];
#pragma unroll
            for (int half = 0; half < 2; half++) {
                int nf = 2 * kc + half;
                pah[half * 2 + 0] = packh(__float2half_rn(sc[nf][0]),
                                          __float2half_rn(sc[nf][1]));
                pah[half * 2 + 1] = packh(__float2half_rn(sc[nf][2]),
                                          __float2half_rn(sc[nf][3]));
            }
            int vrow = kc * 16 + vrowbase;
#pragma unroll
            for (int g = 0; g < 4; g++) {
                int vcol = g * 16 + kcolsel;
                uint32_t v4h[4];
                ldsm4t(v4h, sptr(VH + vrow * ASTR + vcol));
                mmah(oc[2 * g],     pah, v4h[0], v4h[2]);
                mmah(oc[2 * g + 1], pah, v4h[1], v4h[3]);
            }
        }
    }

    l0 += __shfl_xor_sync(0xffffffffu, l0, 1);
    l0 += __shfl_xor_sync(0xffffffffu, l0, 2);
    l1 += __shfl_xor_sync(0xffffffffu, l1, 1);
    l1 += __shfl_xor_sync(0xffffffffu, l1, 2);

    float inv0 = 1.f / l0, inv1 = 1.f / l1;
    int row0 = q0 + w * 16 + (lane >> 2);
    size_t ob = (size_t)b * SL * ET;
#pragma unroll
    for (int nf = 0; nf < 8; nf++) {
        int col = hoff + nf * 8 + (lane & 3) * 2;
        size_t i0 = ob + (size_t)row0 * ET + col;
        size_t i1 = ob + (size_t)(row0 + 8) * ET + col;
        *(__half2*)(g_oh + i0) = __halves2half2(
            __float2half_rn(oc[nf][0] * inv0), __float2half_rn(oc[nf][1] * inv0));
        *(__half2*)(g_oh + i1) = __halves2half2(
            __float2half_rn(oc[nf][2] * inv1), __float2half_rn(oc[nf][3] * inv1));
    }
}

// ---------------- launch ----------------
extern "C" void kernel_launch(void* const* d_in, const int* in_sizes, int n_in,
                              void* d_out, int out_size)
{
    const float* query = (const float*)d_in[0];
    const float* Wqkv  = (const float*)d_in[3];
    const float* bqkv  = (const float*)d_in[4];
    const float* Wo    = (const float*)d_in[5];
    const float* bo    = (const float*)d_in[6];
    const float* Xi    = (const float*)d_in[7];
    float* out = (float*)d_out;

    fp16 *qh, *wh, *wl, *qkvh, *oh, *weh;
    cudaGetSymbolAddress((void**)&qh, g_qh);
    cudaGetSymbolAddress((void**)&wh, g_wh);
    cudaGetSymbolAddress((void**)&wl, g_wl);
    cudaGetSymbolAddress((void**)&qkvh, g_qkvh);
    cudaGetSymbolAddress((void**)&oh, g_oh);
    cudaGetSymbolAddress((void**)&weh, g_weffh);

    constexpr int SM2 = 2 * 26624 * 2;   // P==2: (9216 + 2*8704) fp16 per stage
    constexpr int SM1 = 2 * 17920 * 2;   // P==1: (9216 + 8704) fp16 per stage
    cudaFuncSetAttribute(mma_gemm<2>, cudaFuncAttributeMaxDynamicSharedMemorySize, SM2);
    cudaFuncSetAttribute(mma_gemm<1>, cudaFuncAttributeMaxDynamicSharedMemorySize, SM1);
    cudaFuncSetAttribute(attn_kernel, cudaFuncAttributeMaxDynamicSharedMemorySize, ATTN_SMEM);
    cudaFuncSetAttribute(prep_kernel, cudaFuncAttributeMaxDynamicSharedMemorySize, PREP_SMEM);

    // 0) prep: fp16 splits (blocks >=128) concurrent with powweff (blocks 0..127)
    prep_kernel<<<PREP_PW_BLOCKS + PREP_SPLIT_BLOCKS, 256, PREP_SMEM>>>(
        query, Wqkv, Xi, Wo, qh, wh, wl);

    // 1) QKV projection (2-product, BK=64) -> fp16 qkv, q cols scaled by log2e/8
    dim3 g1(3 * ET / 128, NB * SL / 128, 1);
    mma_gemm<2><<<g1, 256, SM2>>>(qh, wh, wl, bqkv, nullptr, qkvh, EQ,
                                  NB * SL, 3 * ET, EQ, 0, 0, (size_t)0);

    // 2) causal flash attention (ex2 softmax) -> fp16 attn out
    attn_kernel<<<dim3(SL / 128, NB * NH), 256, ATTN_SMEM>>>();

    // 3) fused forecast+output projection (1-product, BK=64) -> fp32 out
    dim3 g2(EQ / 128, SL / 128, NB * NF);
    mma_gemm<1><<<g2, 256, SM1>>>(oh, weh, nullptr, bo, out, nullptr, 0,
                                  SL, EQ, ET,
                                  (size_t)SL * ET, (size_t)ET * EQ, (size_t)SL * EQ);
}

// round 13
// speedup vs baseline: 1.3641x; 1.2085x over previous
#include <cuda_runtime.h>
#include <cuda_fp16.h>
#include <cstdint>

#define NB 4
#define SL 2048
#define EQ 512
#define ET 512
#define NH 8
#define EH 64
#define NF 8

typedef __half fp16;

// q pre-scale includes log2(e): (1/8)*log2(e); attention uses raw ex2
#define QSCALE 0.18033688f
#define EXP2_OFF 5.7707802f     // 4 * log2(e)

// ---------------- scratch (device globals; no allocation allowed) ----------------
__device__ __align__(16) fp16 g_qh   [NB * SL * EQ];
__device__ __align__(16) fp16 g_wh   [EQ * 3 * ET];
__device__ __align__(16) fp16 g_qkvh [NB * SL * 3 * ET];
__device__ __align__(16) fp16 g_oh   [NB * SL * ET];
__device__ __align__(16) fp16 g_weffh[NF * ET * EQ];

// ---------------- PTX helpers ----------------
__device__ __forceinline__ uint32_t sptr(const void* p) {
    return (uint32_t)__cvta_generic_to_shared(p);
}
__device__ __forceinline__ void cpasync16(uint32_t s, const void* g) {
    asm volatile("cp.async.cg.shared.global [%0], [%1], 16;\n" :: "r"(s), "l"(g));
}
__device__ __forceinline__ void cpcommit() {
    asm volatile("cp.async.commit_group;\n");
}
template<int N> __device__ __forceinline__ void cpwait() {
    asm volatile("cp.async.wait_group %0;\n" :: "n"(N));
}
__device__ __forceinline__ void ldsm4(uint32_t* r, uint32_t a) {
    asm volatile("ldmatrix.sync.aligned.m8n8.x4.shared.b16 {%0,%1,%2,%3},[%4];\n"
                 : "=r"(r[0]), "=r"(r[1]), "=r"(r[2]), "=r"(r[3]) : "r"(a));
}
__device__ __forceinline__ void ldsm4t(uint32_t* r, uint32_t a) {
    asm volatile("ldmatrix.sync.aligned.m8n8.x4.trans.shared.b16 {%0,%1,%2,%3},[%4];\n"
                 : "=r"(r[0]), "=r"(r[1]), "=r"(r[2]), "=r"(r[3]) : "r"(a));
}
__device__ __forceinline__ void mmah(float* c, const uint32_t* a, uint32_t b0, uint32_t b1) {
    asm volatile("mma.sync.aligned.m16n8k16.row.col.f32.f16.f16.f32 "
                 "{%0,%1,%2,%3},{%4,%5,%6,%7},{%8,%9},{%0,%1,%2,%3};\n"
                 : "+f"(c[0]), "+f"(c[1]), "+f"(c[2]), "+f"(c[3])
                 : "r"(a[0]), "r"(a[1]), "r"(a[2]), "r"(a[3]), "r"(b0), "r"(b1));
}
__device__ __forceinline__ uint32_t packh(fp16 a, fp16 b) {
    __half2 t = __halves2half2(a, b);
    return *(uint32_t*)&t;
}
__device__ __forceinline__ float ex2(float x) {
    float y;
    asm("ex2.approx.ftz.f32 %0, %1;" : "=f"(y) : "f"(x));
    return y;
}

// ---------------- split: query + Wqkv -> single fp16 ----------------
#define NQ4 (NB * SL * EQ / 4)
#define NW4 (EQ * 3 * ET / 4)

__global__ void __launch_bounds__(256)
split_kernel(const float* __restrict__ query, const float* __restrict__ Wqkv,
             fp16* __restrict__ qh, fp16* __restrict__ wh)
{
    int i = blockIdx.x * 256 + threadIdx.x;
    if (i < NQ4) {
        float4 v = ((const float4*)query)[i];
        ((__half2*)qh)[2 * i]     = __halves2half2(__float2half_rn(v.x), __float2half_rn(v.y));
        ((__half2*)qh)[2 * i + 1] = __halves2half2(__float2half_rn(v.z), __float2half_rn(v.w));
    } else if (i < NQ4 + NW4) {
        int j = i - NQ4;
        float4 v = ((const float4*)Wqkv)[j];
        ((__half2*)wh)[2 * j]     = __halves2half2(__float2half_rn(v.x), __float2half_rn(v.y));
        ((__half2*)wh)[2 * j + 1] = __halves2half2(__float2half_rn(v.z), __float2half_rn(v.w));
    }
}

// ---------------- fp16 tensor-core GEMM, 128x128 tiles, BK=64, 2 stages ----------
// 1-product: C = Ah·Bh (+bias). Used for both gemm1 (fp16 out, q-scale) and gemm2.
__global__ void __launch_bounds__(256)
mma_gemm(const fp16* __restrict__ Ah_, const fp16* __restrict__ Bh_,
         const float* __restrict__ bias, float* __restrict__ C,
         fp16* __restrict__ Ch, int qscaleCols,
         int M, int N, int K, size_t aB, size_t bB, size_t cB)
{
    constexpr int BHOc = 9216;                  // A = 128*72
    constexpr int GSc  = BHOc + 8704;           // + B = 64*136

    extern __shared__ fp16 sm[];
    int z = blockIdx.z;
    Ah_ += (size_t)(z >> 3) * aB;
    Bh_ += (size_t)(z & 7) * bB;

    int tid = threadIdx.x, lane = tid & 31, wid = tid >> 5;
    int wm = wid >> 2, wn = wid & 3;
    int m0 = blockIdx.y * 128, n0c = blockIdx.x * 128;
    uint32_t sbase = sptr(sm);

    int chunk = tid & 7, rowa = tid >> 3;
    int ckb = tid & 15, rowb = tid >> 4;

    auto loadTile = [&](int kt, int buf) {
        int k0 = kt * 64;
        uint32_t sb = sbase + buf * GSc * 2;
#pragma unroll
        for (int rep = 0; rep < 4; rep++) {
            int r = rowa + rep * 32;
            cpasync16(sb + (r * 72 + chunk * 8) * 2,
                      Ah_ + (size_t)(m0 + r) * K + k0 + chunk * 8);
        }
#pragma unroll
        for (int rep = 0; rep < 4; rep++) {
            int r = rowb + rep * 16;
            cpasync16(sb + (BHOc + r * 136 + ckb * 8) * 2,
                      Bh_ + (size_t)(k0 + r) * N + n0c + ckb * 8);
        }
        cpcommit();
    };

    float acc[4][4][4];
#pragma unroll
    for (int i = 0; i < 4; i++)
#pragma unroll
        for (int j = 0; j < 4; j++)
#pragma unroll
            for (int k = 0; k < 4; k++) acc[i][j][k] = 0.f;

    int arow = wm * 64 + (lane & 15);
    int acolsel = (lane >> 4) << 3;
    int krow = (lane & 7) + ((lane >> 4) << 3);
    int bcol = wn * 32 + ((lane >> 3) & 1) * 8;

    int nk = K / 64;
    loadTile(0, 0);
    for (int kt = 0; kt < nk; kt++) {
        if (kt + 1 < nk) { loadTile(kt + 1, (kt + 1) & 1); cpwait<1>(); }
        else             { cpwait<0>(); }
        __syncthreads();
        uint32_t sb = sbase + (kt & 1) * GSc * 2;

#pragma unroll
        for (int ks = 0; ks < 4; ks++) {
            int acol = ks * 16 + acolsel;
            uint32_t ah[4][4];
#pragma unroll
            for (int mi = 0; mi < 4; mi++)
                ldsm4(ah[mi], sb + ((arow + mi * 16) * 72 + acol) * 2);
            uint32_t bh[2][4];
            int brow = ks * 16 + krow;
#pragma unroll
            for (int g = 0; g < 2; g++)
                ldsm4t(bh[g], sb + (BHOc + brow * 136 + bcol + g * 16) * 2);
#pragma unroll
            for (int mi = 0; mi < 4; mi++)
#pragma unroll
                for (int nf = 0; nf < 4; nf++) {
                    int g = nf >> 1, s = nf & 1;
                    mmah(acc[mi][nf], ah[mi], bh[g][s], bh[g][s + 2]);
                }
        }
        __syncthreads();
    }

#pragma unroll
    for (int mi = 0; mi < 4; mi++)
#pragma unroll
        for (int nf = 0; nf < 4; nf++) {
            int r = m0 + wm * 64 + mi * 16 + (lane >> 2);
            int c = n0c + wn * 32 + nf * 8 + (lane & 3) * 2;
            float b0 = bias[c], b1 = bias[c + 1];
            float v00 = acc[mi][nf][0] + b0, v01 = acc[mi][nf][1] + b1;
            float v10 = acc[mi][nf][2] + b0, v11 = acc[mi][nf][3] + b1;
            if (qscaleCols && c < qscaleCols) {
                v00 *= QSCALE; v01 *= QSCALE; v10 *= QSCALE; v11 *= QSCALE;
            }
            if (Ch) {
                size_t i0 = (size_t)z * cB + (size_t)r * N + c;
                size_t i1 = i0 + (size_t)8 * N;
                *(__half2*)(Ch + i0) = __halves2half2(__float2half_rn(v00), __float2half_rn(v01));
                *(__half2*)(Ch + i1) = __halves2half2(__float2half_rn(v10), __float2half_rn(v11));
            } else {
                float* Cz = C + (size_t)z * cB;
                *(float2*)(Cz + (size_t)r * N + c) = make_float2(v00, v01);
                *(float2*)(Cz + (size_t)(r + 8) * N + c) = make_float2(v10, v11);
            }
        }
}

// ---------------- powweff device function (runs inside attention launch) ----------
__device__ void powweff_body(float* pw, const float* __restrict__ Xi,
                             const float* __restrict__ Wo, int idx)
{
    float* Mh = pw;
    float* R  = pw + 4352;
    float* RT = pw + 2 * 4352;
    int half = idx & 1;
    int nh = idx >> 1;
    int n = nh >> 3, h = nh & 7;
    int tid = threadIdx.x;
    const float* X = Xi + h * 64 * 64;

#pragma unroll
    for (int t = 0; t < 16; t++) {
        int id2 = tid + t * 256;
        int i = id2 >> 6, j = id2 & 63;
        float v = X[i * 64 + j] - X[j * 64 + i];
        if (i == j) v += 1.f;
        Mh[i * 68 + j] = v;
        R [i * 68 + j] = v;
        RT[j * 68 + i] = v;
    }
    __syncthreads();

    int i0 = (tid >> 4) * 4, j0 = (tid & 15) * 4;
    auto mult = [&](const float* B) {
        float acc[4][4];
#pragma unroll
        for (int a = 0; a < 4; a++)
#pragma unroll
            for (int bq = 0; bq < 4; bq++) acc[a][bq] = 0.f;
#pragma unroll 4
        for (int k = 0; k < 64; k++) {
            float4 av = *(const float4*)&RT[k * 68 + i0];
            float4 bv = *(const float4*)&B[k * 68 + j0];
            float aa[4] = {av.x, av.y, av.z, av.w};
            float bb[4] = {bv.x, bv.y, bv.z, bv.w};
#pragma unroll
            for (int a = 0; a < 4; a++)
#pragma unroll
                for (int bq = 0; bq < 4; bq++)
                    acc[a][bq] = fmaf(aa[a], bb[bq], acc[a][bq]);
        }
        __syncthreads();
#pragma unroll
        for (int a = 0; a < 4; a++)
#pragma unroll
            for (int bq = 0; bq < 4; bq++) {
                R [(i0 + a) * 68 + j0 + bq] = acc[a][bq];
                RT[(j0 + bq) * 68 + i0 + a] = acc[a][bq];
            }
        __syncthreads();
    };

    int e = n + 1;
    if (e > 1) {
        int msb = 31 - __clz(e);
        for (int bpos = msb - 1; bpos >= 0; bpos--) {
            mult(R);
            if ((e >> bpos) & 1) mult(Mh);
        }
    }

    int c = half * 256 + tid;
    const float* WoH = Wo + (size_t)h * 64 * EQ;
    size_t ob = (size_t)n * ET * EQ + (size_t)h * 64 * EQ;
    float acc[4][16];
#pragma unroll
    for (int p = 0; p < 4; p++)
#pragma unroll
        for (int ii = 0; ii < 16; ii++) acc[p][ii] = 0.f;
    for (int j = 0; j < 64; j++) {
        float wv = WoH[j * EQ + c];
        const float* row = &RT[j * 68];
#pragma unroll
        for (int p = 0; p < 4; p++) {
#pragma unroll
            for (int q4 = 0; q4 < 4; q4++) {
                float4 rv = *(const float4*)&row[p * 16 + q4 * 4];
                acc[p][q4 * 4 + 0] = fmaf(rv.x, wv, acc[p][q4 * 4 + 0]);
                acc[p][q4 * 4 + 1] = fmaf(rv.y, wv, acc[p][q4 * 4 + 1]);
                acc[p][q4 * 4 + 2] = fmaf(rv.z, wv, acc[p][q4 * 4 + 2]);
                acc[p][q4 * 4 + 3] = fmaf(rv.w, wv, acc[p][q4 * 4 + 3]);
            }
        }
    }
#pragma unroll
    for (int p = 0; p < 4; p++)
#pragma unroll
        for (int ii = 0; ii < 16; ii++)
            g_weffh[ob + (size_t)(p * 16 + ii) * EQ + c] = __float2half_rn(acc[p][ii]);
}

// ---------------- attention + powweff, one launch ----------------
// blocks [0,128): powweff (scheduled first, hides under attention)
// blocks [128,640): causal flash attention, d=64, BQ=128, BKV=64,
//   ex2 static-offset softmax, 3-stage cp.async pipe, hoisted Q frags.
#define ASTR 72
#define QH_OFF 0
#define KV_OFF 9216
#define KVSTAGE 9216
#define ATTN_SMEM ((9216 + 3 * 9216) * 2)   // 73728 B >= powweff's 52224 B
#define PW_BLOCKS (2 * NF * NH)             // 128

__global__ void __launch_bounds__(256, 2)
attn_pow_kernel(const float* __restrict__ Xi, const float* __restrict__ Wo)
{
    extern __shared__ fp16 smb[];
    if (blockIdx.x < PW_BLOCKS) {
        powweff_body((float*)smb, Xi, Wo, blockIdx.x);
        return;
    }
    int ab = blockIdx.x - PW_BLOCKS;
    int qt = 15 - (ab & 15);
    int bh = ab >> 4;
    int b = bh >> 3, h = bh & 7;
    int tid = threadIdx.x, lane = tid & 31, w = tid >> 5;
    int q0 = qt * 128;
    int hoff = h * EH;
    const fp16* qkvh = g_qkvh + (size_t)b * SL * 1536;

    {
        int chunk = tid & 7;
        int row = tid >> 3;
#pragma unroll
        for (int it = 0; it < 4; it++) {
            int r = row + it * 32;
            cpasync16(sptr(smb + QH_OFF + r * ASTR + chunk * 8),
                      qkvh + (size_t)(q0 + r) * 1536 + hoff + chunk * 8);
        }
    }
    auto loadKV = [&](int kt, int stage) {
        int kv0 = kt * 64;
        fp16* base = smb + KV_OFF + stage * KVSTAGE;
        int chunk = tid & 7;
        int row = tid >> 3;
#pragma unroll
        for (int it = 0; it < 4; it++) {
            int arr = it >> 1;
            int r = row + (it & 1) * 32;
            int colbase = (arr == 0) ? (ET + hoff) : (2 * ET + hoff);
            cpasync16(sptr(base + arr * 4608 + r * ASTR + chunk * 8),
                      qkvh + (size_t)(kv0 + r) * 1536 + colbase + chunk * 8);
        }
        cpcommit();
    };

    int kmax = 2 * qt + 1;
    loadKV(0, 0);
    loadKV(1, 1);

    float l0 = 0.f, l1 = 0.f;
    float oc[8][4];
#pragma unroll
    for (int i = 0; i < 8; i++)
#pragma unroll
        for (int j = 0; j < 4; j++) oc[i][j] = 0.f;

    int arow = w * 16 + (lane & 15);
    int acolsel = (lane >> 4) << 3;
    int krow = (lane & 7) + ((lane >> 4) << 3);
    int kcolsel = ((lane >> 3) & 1) << 3;
    int vrowbase = krow;

    cpwait<1>();
    __syncthreads();

    uint32_t qf[4][4];
#pragma unroll
    for (int kc = 0; kc < 4; kc++)
        ldsm4(qf[kc], sptr(smb + QH_OFF + arow * ASTR + kc * 16 + acolsel));

    for (int kt = 0; kt <= kmax; kt++) {
        if (kt > 0) {
            cpwait<1>();
            __syncthreads();
        }
        if (kt + 2 <= kmax) loadKV(kt + 2, (kt + 2) % 3);
        else                cpcommit();

        fp16* base = smb + KV_OFF + (kt % 3) * KVSTAGE;
        fp16* KH = base;
        fp16* VH = base + 4608;

        float sc[8][4];
#pragma unroll
        for (int i = 0; i < 8; i++)
#pragma unroll
            for (int j = 0; j < 4; j++) sc[i][j] = 0.f;

#pragma unroll
        for (int kc = 0; kc < 4; kc++) {
            int kcol = kc * 16 + kcolsel;
#pragma unroll
            for (int g = 0; g < 4; g++) {
                uint32_t b4h[4];
                ldsm4(b4h, sptr(KH + (g * 16 + krow) * ASTR + kcol));
                mmah(sc[2 * g],     qf[kc], b4h[0], b4h[1]);
                mmah(sc[2 * g + 1], qf[kc], b4h[2], b4h[3]);
            }
        }

        if (kt >= 2 * qt) {
            int kv0 = kt * 64;
            int r0 = q0 + w * 16 + (lane >> 2);
#pragma unroll
            for (int nf = 0; nf < 8; nf++) {
                int c0 = kv0 + nf * 8 + (lane & 3) * 2;
                if (c0 > r0)     sc[nf][0] = -1e30f;
                if (c0 + 1 > r0) sc[nf][1] = -1e30f;
                if (c0 > r0 + 8)     sc[nf][2] = -1e30f;
                if (c0 + 1 > r0 + 8) sc[nf][3] = -1e30f;
            }
        }

#pragma unroll
        for (int nf = 0; nf < 8; nf++) {
            sc[nf][0] = ex2(sc[nf][0] - EXP2_OFF);
            sc[nf][1] = ex2(sc[nf][1] - EXP2_OFF);
            sc[nf][2] = ex2(sc[nf][2] - EXP2_OFF);
            sc[nf][3] = ex2(sc[nf][3] - EXP2_OFF);
            l0 += sc[nf][0] + sc[nf][1];
            l1 += sc[nf][2] + sc[nf][3];
        }

#pragma unroll
        for (int kc = 0; kc < 4; kc++) {
            uint32_t pah[4];
#pragma unroll
            for (int half = 0; half < 2; half++) {
                int nf = 2 * kc + half;
                pah[half * 2 + 0] = packh(__float2half_rn(sc[nf][0]),
                                          __float2half_rn(sc[nf][1]));
                pah[half * 2 + 1] = packh(__float2half_rn(sc[nf][2]),
                                          __float2half_rn(sc[nf][3]));
            }
            int vrow = kc * 16 + vrowbase;
#pragma unroll
            for (int g = 0; g < 4; g++) {
                int vcol = g * 16 + kcolsel;
                uint32_t v4h[4];
                ldsm4t(v4h, sptr(VH + vrow * ASTR + vcol));
                mmah(oc[2 * g],     pah, v4h[0], v4h[2]);
                mmah(oc[2 * g + 1], pah, v4h[1], v4h[3]);
            }
        }
    }

    l0 += __shfl_xor_sync(0xffffffffu, l0, 1);
    l0 += __shfl_xor_sync(0xffffffffu, l0, 2);
    l1 += __shfl_xor_sync(0xffffffffu, l1, 1);
    l1 += __shfl_xor_sync(0xffffffffu, l1, 2);

    float inv0 = 1.f / l0, inv1 = 1.f / l1;
    int row0 = q0 + w * 16 + (lane >> 2);
    size_t ob = (size_t)b * SL * ET;
#pragma unroll
    for (int nf = 0; nf < 8; nf++) {
        int col = hoff + nf * 8 + (lane & 3) * 2;
        size_t i0 = ob + (size_t)row0 * ET + col;
        size_t i1 = ob + (size_t)(row0 + 8) * ET + col;
        *(__half2*)(g_oh + i0) = __halves2half2(
            __float2half_rn(oc[nf][0] * inv0), __float2half_rn(oc[nf][1] * inv0));
        *(__half2*)(g_oh + i1) = __halves2half2(
            __float2half_rn(oc[nf][2] * inv1), __float2half_rn(oc[nf][3] * inv1));
    }
}

// ---------------- launch ----------------
extern "C" void kernel_launch(void* const* d_in, const int* in_sizes, int n_in,
                              void* d_out, int out_size)
{
    const float* query = (const float*)d_in[0];
    const float* Wqkv  = (const float*)d_in[3];
    const float* bqkv  = (const float*)d_in[4];
    const float* Wo    = (const float*)d_in[5];
    const float* bo    = (const float*)d_in[6];
    const float* Xi    = (const float*)d_in[7];
    float* out = (float*)d_out;

    fp16 *qh, *wh, *qkvh, *oh, *weh;
    cudaGetSymbolAddress((void**)&qh, g_qh);
    cudaGetSymbolAddress((void**)&wh, g_wh);
    cudaGetSymbolAddress((void**)&qkvh, g_qkvh);
    cudaGetSymbolAddress((void**)&oh, g_oh);
    cudaGetSymbolAddress((void**)&weh, g_weffh);

    constexpr int SM1 = 2 * 17920 * 2;   // (9216 + 8704) fp16 per stage, 2 stages
    cudaFuncSetAttribute(mma_gemm, cudaFuncAttributeMaxDynamicSharedMemorySize, SM1);
    cudaFuncSetAttribute(attn_pow_kernel, cudaFuncAttributeMaxDynamicSharedMemorySize, ATTN_SMEM);

    // 0) fp16 splits (query, Wqkv — both single fp16)
    split_kernel<<<(NQ4 + NW4 + 255) / 256, 256>>>(query, Wqkv, qh, wh);

    // 1) QKV projection (1-product) -> fp16 qkv, q cols scaled by log2e/8
    dim3 g1(3 * ET / 128, NB * SL / 128, 1);
    mma_gemm<<<g1, 256, SM1>>>(qh, wh, bqkv, nullptr, qkvh, EQ,
                               NB * SL, 3 * ET, EQ, 0, 0, (size_t)0);

    // 2) attention + powweff in one launch (powweff blocks first)
    attn_pow_kernel<<<PW_BLOCKS + 16 * NB * NH, 256, ATTN_SMEM>>>(Xi, Wo);

    // 3) fused forecast+output projection (1-product) -> fp32 out
    dim3 g2(EQ / 128, SL / 128, NB * NF);
    mma_gemm<<<g2, 256, SM1>>>(oh, weh, bo, out, nullptr, 0,
                               SL, EQ, ET,
                               (size_t)SL * ET, (size_t)ET * EQ, (size_t)SL * EQ);
}